// round 14
// baseline (speedup 1.0000x reference)
#include <cuda_runtime.h>
#include <math.h>
#include <float.h>
#include <stdint.h>

// Problem constants: predicts [B,T,C] f32, labels [B,L] i32 in [1,C),
// label_lengths [B] i32 in [1,L].
constexpr int B = 128;
constexpr int T = 128;
constexpr int C = 6625;
constexpr int L = 25;
constexpr int S = 2 * L + 1;   // 51 extended states
constexpr int NE = L + 1;      // emit slots: blank + L labels
constexpr float NEGV  = -1e30f;
constexpr float LOG2E = 1.4426950408889634f;
constexpr float LN2   = 0.6931471805599453f;

constexpr int K1B  = 1088;     // streaming blocks
constexpr int GRID = K1B + B;  // 1216 = 8 CTAs x 152 SMs -> ONE wave
constexpr int TMID = 64;       // forward [0,64), backward [64,128)

// Scratch (static device globals; no allocation allowed)
__device__ __align__(16) float g_emit[(size_t)B * T * NE]; // base-2 log emit
__device__ float    g_partial[B];
__device__ unsigned g_rowcnt[B];             // reset in-kernel after use
__device__ int      g_dpcnt;                 // never reset: modulo-B test

__device__ __forceinline__ float ex2f(float x) {
    float y; asm("ex2.approx.ftz.f32 %0, %1;" : "=f"(y) : "f"(x)); return y;
}
__device__ __forceinline__ float lg2f(float x) {
    float y; asm("lg2.approx.ftz.f32 %0, %1;" : "=f"(y) : "f"(x)); return y;
}

// ---------------------------------------------------------------------------
// Single-wave fused kernel.
//  blocks [0, K1B):  persistent row logsumexp + gather (verified R13 math);
//                    after each row, publish via red.release.gpu on rowcnt.
//  blocks [K1B, GRID): dp block for batch b = bid-K1B; spin-wait (acquire +
//                    nanosleep) until all T rows of b arrive, then run the
//                    verified fwd/bwd log2 CTC recursion; fused final reduce.
// ---------------------------------------------------------------------------
__global__ __launch_bounds__(256, 8) void k_all(
    const float* __restrict__ pred, const int* __restrict__ labels,
    const int* __restrict__ lens, float* __restrict__ out)
{
    const int tid  = threadIdx.x;
    const int lane = tid & 31;
    const int wid  = tid >> 5;

    __shared__ float sw[2][8];
    __shared__ __align__(16) float se[T * NE + 32];
    __shared__ float s_a0[32], s_a1[32], s_b0[32], s_b1[32];
    __shared__ float s_fin[4];
    __shared__ int   s_flag;

    if (blockIdx.x < K1B) {
        // ================= streaming phase ==========================
        int par = 0;
        for (int bt = blockIdx.x; bt < B * T; bt += K1B, par ^= 1) {
            const int b = bt / T;
            const float* row = pred + (size_t)bt * C;

            const int idx0 = (4 - (bt & 3)) & 3;   // peel to 16B alignment
            const int n4   = (C - idx0) >> 2;
            const float4* vrow = (const float4*)(row + idx0);

            float4 v[7];
#pragma unroll
            for (int k = 0; k < 7; k++) {          // batched -> high MLP
                int i = tid + k * 256;
                v[k] = (i < n4) ? __ldg(vrow + i)
                                : make_float4(-FLT_MAX, -FLT_MAX, -FLT_MAX, -FLT_MAX);
            }
            float s = 0.f;
#pragma unroll
            for (int k = 0; k < 7; k++) {
                s += __expf(v[k].x); s += __expf(v[k].y);
                s += __expf(v[k].z); s += __expf(v[k].w);
            }
            if (tid == 0) {                        // head + tail scalars
                for (int i = 0; i < idx0; i++)           s += __expf(__ldg(row + i));
                for (int i = idx0 + 4 * n4; i < C; i++)  s += __expf(__ldg(row + i));
            }
#pragma unroll
            for (int o = 16; o > 0; o >>= 1)
                s += __shfl_xor_sync(0xffffffffu, s, o);

            if (lane == 0) sw[par][wid] = s;
            __syncthreads();   // warps run ahead; they write sw[par^1] next.

            if (tid < NE) {                        // all in warp 0
                float tot = 0.f;
#pragma unroll
                for (int w = 0; w < 8; w++) tot += sw[par][w];
                float lse2 = lg2f(tot);            // log2(sum exp)
                int cls = (tid == 0) ? 0 : labels[b * L + tid - 1];
                g_emit[(size_t)bt * NE + tid] = fmaf(__ldg(row + cls), LOG2E, -lse2);
            }
            if (tid < 32) {                        // publish row: release
                __syncwarp();                      // lanes 0..25 stores done
                if (tid == 0)
                    asm volatile("red.release.gpu.global.add.u32 [%0], %1;"
                                 :: "l"(&g_rowcnt[b]), "r"(1u) : "memory");
            }
        }
        return;
    }

    // ==================== dp phase ==================================
    const int b = blockIdx.x - K1B;

    if (tid == 0) {                                // wait for all T rows of b
        unsigned v;
        while (true) {
            asm volatile("ld.acquire.gpu.global.u32 %0, [%1];"
                         : "=r"(v) : "l"(&g_rowcnt[b]) : "memory");
            if (v >= (unsigned)T) break;
            __nanosleep(128);
        }
        g_rowcnt[b] = 0;                           // reset for next replay
    }
    __syncthreads();                               // acquire propagates to block

    {   // stage emit tile: 832 float4 over 256 threads
        const float4* src4 = (const float4*)(g_emit + (size_t)b * T * NE);
        float4* se4 = (float4*)se;
#pragma unroll
        for (int i = tid; i < (T * NE) / 4; i += 256) se4[i] = src4[i];
        if (tid < 32) se[T * NE + tid] = NEGV;     // init pad
    }
    __syncthreads();

    if (wid == 0) {
        // -------- forward alpha: t = 0 .. TMID-1 (shfl_up) ----------
        int lab  = (lane < L) ? labels[b * L + lane] : -999;
        int labp = __shfl_up_sync(0xffffffffu, lab, 1);
        const bool skip1 = (lane >= 1 && lane < L && lab != labp);
        const bool act1  = (lane <= 24);           // s1 = 2*lane+1 < S

        float a0 = (lane == 0) ? se[0] : NEGV;
        float a1 = (lane == 0) ? se[1] : NEGV;

        float e0n = se[NE];
        float e1n = se[NE + lane + 1];

        for (int t = 1; t < TMID; t++) {
            const float e0 = e0n, e1 = e1n;
            e0n = se[(t + 1) * NE];
            e1n = se[(t + 1) * NE + lane + 1];

            float p1 = __shfl_up_sync(0xffffffffu, a1, 1);
            if (lane == 0) p1 = NEGV;

            float mm0 = fmaxf(a0, p1);
            float na0 = mm0 + lg2f(ex2f(a0 - mm0) + ex2f(p1 - mm0)) + e0;

            float c   = skip1 ? p1 : NEGV;
            float mm1 = fmaxf(fmaxf(a1, a0), c);
            float na1 = mm1
                + lg2f(ex2f(a1 - mm1) + ex2f(a0 - mm1) + ex2f(c - mm1)) + e1;

            a0 = na0;
            a1 = act1 ? na1 : NEGV;
        }
        s_a0[lane] = a0;
        s_a1[lane] = a1;
    } else if (wid == 1) {
        // -------- backward beta: t = T-1 .. TMID (shfl_down) --------
        int lab  = (lane < L) ? labels[b * L + lane] : -999;
        int labn = __shfl_down_sync(0xffffffffu, lab, 1);
        const bool skipd = (lane <= 23) && (labn != lab);
        const bool act0  = (lane <= 25);
        const bool act1  = (lane <= 24);

        const int len = lens[b];
        float b0 = (lane == len)     ? se[(T - 1) * NE]            : NEGV;
        float b1 = (lane == len - 1) ? se[(T - 1) * NE + lane + 1] : NEGV;

        float e0n = se[(T - 2) * NE];
        float e1n = se[(T - 2) * NE + lane + 1];

        for (int t = T - 2; t >= TMID; t--) {
            const float e0 = e0n, e1 = e1n;
            e0n = se[(t - 1) * NE];
            e1n = se[(t - 1) * NE + lane + 1];

            float q0 = __shfl_down_sync(0xffffffffu, b0, 1);
            float q1 = __shfl_down_sync(0xffffffffu, b1, 1);

            float mm0 = fmaxf(b0, b1);
            float nb0 = mm0 + lg2f(ex2f(b0 - mm0) + ex2f(b1 - mm0)) + e0;

            float c   = skipd ? q1 : NEGV;
            float mm1 = fmaxf(fmaxf(b1, q0), c);
            float nb1 = mm1
                + lg2f(ex2f(b1 - mm1) + ex2f(q0 - mm1) + ex2f(c - mm1)) + e1;

            b0 = act0 ? nb0 : NEGV;
            b1 = act1 ? nb1 : NEGV;
        }
        s_b0[lane] = b0;
        s_b1[lane] = b1;
    }
    __syncthreads();

    if (wid == 0) {
        // combine: ll2 = LSE2_s( alpha[s] + beta[s] )
        float ta = s_a0[lane] + s_b0[lane];
        float tb = s_a1[lane] + s_b1[lane];
        float m = fmaxf(ta, tb);
#pragma unroll
        for (int o = 16; o > 0; o >>= 1)
            m = fmaxf(m, __shfl_xor_sync(0xffffffffu, m, o));
        float sum = ex2f(ta - m) + ex2f(tb - m);
#pragma unroll
        for (int o = 16; o > 0; o >>= 1)
            sum += __shfl_xor_sync(0xffffffffu, sum, o);
        if (lane == 0) {
            int len = lens[b];
            float ll = (m + lg2f(sum)) * LN2;
            float loss = -ll;
            if (!(loss <= 1e29f)) loss = 0.f;      // zero_infinity (inf/nan)
            g_partial[b] = loss / (float)len;
        }
    }

    // ----- last-arriving dp block (of 128) does the final reduce -----
    __syncthreads();
    if (tid == 0) {
        __threadfence();
        int old = atomicAdd(&g_dpcnt, 1);
        s_flag = ((old % B) == B - 1);
    }
    __syncthreads();
    if (!s_flag) return;
    __threadfence();                               // acquire peer partials

    if (tid < B) {
        float pv = g_partial[tid];
#pragma unroll
        for (int o = 16; o > 0; o >>= 1)
            pv += __shfl_xor_sync(0xffffffffu, pv, o);
        if (lane == 0) s_fin[wid] = pv;
    }
    __syncthreads();
    if (tid == 0)
        out[0] = (s_fin[0] + s_fin[1] + s_fin[2] + s_fin[3])
                 / ((float)B * (float)B);
}

// ---------------------------------------------------------------------------
extern "C" void kernel_launch(void* const* d_in, const int* in_sizes, int n_in,
                              void* d_out, int out_size)
{
    const float* pred   = (const float*)d_in[0];
    const int*   labels = (const int*)d_in[1];
    const int*   lens   = (const int*)d_in[2];
    float*       out    = (float*)d_out;

    k_all<<<GRID, 256>>>(pred, labels, lens, out);
}

// round 15
// speedup vs baseline: 1.0708x; 1.0708x over previous
#include <cuda_runtime.h>
#include <math.h>
#include <float.h>
#include <stdint.h>

// Problem constants: predicts [B,T,C] f32, labels [B,L] i32 in [1,C),
// label_lengths [B] i32 in [1,L].
constexpr int B = 128;
constexpr int T = 128;
constexpr int C = 6625;
constexpr int L = 25;
constexpr int S = 2 * L + 1;   // 51 extended states
constexpr int NE = L + 1;      // emit slots: blank + L labels
constexpr float NEGV  = -1e30f;
constexpr float LOG2E = 1.4426950408889634f;
constexpr float LN2   = 0.6931471805599453f;

constexpr int GRID1 = 1216;    // persistent: 8 CTAs x 152 SMs
constexpr int TMID  = 64;      // forward [0,64), backward [64,128)

// Scratch (static device globals; no allocation allowed)
__device__ __align__(16) float g_emit[(size_t)B * T * NE]; // base-2 log emit
__device__ float g_partial[B];
__device__ int   g_dpcnt;                    // never reset: modulo-B test

__device__ __forceinline__ float ex2f(float x) {
    float y; asm("ex2.approx.ftz.f32 %0, %1;" : "=f"(y) : "f"(x)); return y;
}
__device__ __forceinline__ float lg2f(float x) {
    float y; asm("lg2.approx.ftz.f32 %0, %1;" : "=f"(y) : "f"(x)); return y;
}

// ---------------------------------------------------------------------------
// Kernel 1 (unchanged, verified): persistent-grid row logsumexp + gather.
// ---------------------------------------------------------------------------
__global__ __launch_bounds__(256, 8) void k_lse_gather(
    const float* __restrict__ pred, const int* __restrict__ labels)
{
    const int tid = threadIdx.x;
    __shared__ float sw[2][8];

    int par = 0;
    for (int bt = blockIdx.x; bt < B * T; bt += GRID1, par ^= 1) {
        const int b = bt / T;
        const float* row = pred + (size_t)bt * C;

        const int idx0 = (4 - (bt & 3)) & 3;       // peel to 16B alignment
        const int n4   = (C - idx0) >> 2;
        const float4* vrow = (const float4*)(row + idx0);

        float4 v[7];
#pragma unroll
        for (int k = 0; k < 7; k++) {              // batched -> high MLP
            int i = tid + k * 256;
            v[k] = (i < n4) ? __ldg(vrow + i)
                            : make_float4(-FLT_MAX, -FLT_MAX, -FLT_MAX, -FLT_MAX);
        }
        float s = 0.f;
#pragma unroll
        for (int k = 0; k < 7; k++) {
            s += __expf(v[k].x); s += __expf(v[k].y);
            s += __expf(v[k].z); s += __expf(v[k].w);
        }
        if (tid == 0) {                            // head + tail scalars
            for (int i = 0; i < idx0; i++)           s += __expf(__ldg(row + i));
            for (int i = idx0 + 4 * n4; i < C; i++)  s += __expf(__ldg(row + i));
        }
#pragma unroll
        for (int o = 16; o > 0; o >>= 1)
            s += __shfl_xor_sync(0xffffffffu, s, o);

        if ((tid & 31) == 0) sw[par][tid >> 5] = s;
        __syncthreads();

        if (tid < NE) {                            // all in warp 0
            float tot = 0.f;
#pragma unroll
            for (int w = 0; w < 8; w++) tot += sw[par][w];
            float lse2 = lg2f(tot);                // log2(sum exp)
            int cls = (tid == 0) ? 0 : labels[b * L + tid - 1];
            g_emit[(size_t)bt * NE + tid] = fmaf(__ldg(row + cls), LOG2E, -lse2);
        }
    }
}

// ---------------------------------------------------------------------------
// Kernel 2: forward-backward CTC, log2 domain, with 2-STEP FUSED recursion.
// The banded log-linear recurrence composed over two timesteps gives a
// bandwidth-5 operator whose coefficients depend only on the middle-step
// emissions (off the serial critical path). Warp 0: alpha t=0..63.
// Warp 1: beta t=127..64. Combine ll = LSE_s(alpha_63[s] + beta_64[s]).
// ---------------------------------------------------------------------------
__global__ __launch_bounds__(128) void k_ctc_dp(
    const int* __restrict__ labels, const int* __restrict__ lens,
    float* __restrict__ out)
{
    const int b    = blockIdx.x;
    const int tid  = threadIdx.x;
    const int lane = tid & 31;
    const int wid  = tid >> 5;

    __shared__ __align__(16) float se[T * NE + 64]; // +pad for overreads
    __shared__ float s_a0[32], s_a1[32], s_b0[32], s_b1[32];
    __shared__ float s_fin[4];
    __shared__ int   s_flag;

    {   // stage emit tile: 832 float4 over 128 threads
        const float4* src4 = (const float4*)(g_emit + (size_t)b * T * NE);
        float4* se4 = (float4*)se;
#pragma unroll
        for (int i = tid; i < (T * NE) / 4; i += 128) se4[i] = src4[i];
        if (tid < 64) se[T * NE + tid] = NEGV;      // init pad
    }
    __syncthreads();

    if (wid == 0) {
        // ======== forward alpha: t = 0 .. TMID-1 (fused) ============
        int lab  = (lane < L) ? labels[b * L + lane] : -999;
        int labp = __shfl_up_sync(0xffffffffu, lab, 1);
        const bool skipA = (lane >= 1 && lane < L && lab != labp); // skip into s1=2l+1
        unsigned skBu = __shfl_up_sync(0xffffffffu, (unsigned)skipA, 1);
        const bool skipB = (lane >= 1) && skBu;     // skip of lane-1's odd state
        const bool act1  = (lane <= 24);

        float a0 = (lane == 0) ? se[0] : NEGV;      // alpha[2*lane]
        float a1 = (lane == 0) ? se[1] : NEGV;      // alpha[2*lane+1]

        {   // single step t=1 (verified 1-step form)
            float e0 = se[NE], e1 = se[NE + lane + 1];
            float p1 = __shfl_up_sync(0xffffffffu, a1, 1);
            if (lane == 0) p1 = NEGV;
            float mm0 = fmaxf(a0, p1);
            float na0 = mm0 + lg2f(ex2f(a0 - mm0) + ex2f(p1 - mm0)) + e0;
            float c   = skipA ? p1 : NEGV;
            float mm1 = fmaxf(fmaxf(a1, a0), c);
            float na1 = mm1
                + lg2f(ex2f(a1 - mm1) + ex2f(a0 - mm1) + ex2f(c - mm1)) + e1;
            a0 = na0; a1 = act1 ? na1 : NEGV;
        }

        // 31 double steps: alpha_{tt-1} -> alpha_{tt+1}, mid emits at tt.
        for (int tt = 2; tt < TMID; tt += 2) {
            const float e0p  = se[tt * NE];             // E'[even] (blank)
            const float e1p  = se[tt * NE + lane + 1];  // E'[s1]
            const float e1m  = se[tt * NE + lane];      // E'[s0-1] (lane-1's e1)
            const float e0pp = se[(tt + 1) * NE];       // E''[even]
            const float e1pp = se[(tt + 1) * NE + lane + 1];

            float a0m1 = __shfl_up_sync(0xffffffffu, a0, 1);
            float a1m1 = __shfl_up_sync(0xffffffffu, a1, 1);
            float a1m2 = __shfl_up_sync(0xffffffffu, a1, 2);
            if (lane < 1) { a0m1 = NEGV; a1m1 = NEGV; }
            if (lane < 2) { a1m2 = NEGV; }

            // emission-only coefficients (off the serial chain)
            float mE  = fmaxf(e0p, e1m);
            float cE2 = mE + lg2f(ex2f(e0p - mE) + ex2f(e1m - mE));
            float mO  = fmaxf(e1p, e0p);
            float cO2 = mO + lg2f(ex2f(e1p - mO) + ex2f(e0p - mO));
            float cO3;
            if (skipA) {
                float m3 = fmaxf(fmaxf(e1p, e0p), e1m);
                cO3 = m3 + lg2f(ex2f(e1p - m3) + ex2f(e0p - m3) + ex2f(e1m - m3));
            } else cO3 = e0p;
            const float cE4 = skipB ? e1m : NEGV;
            const float cO4 = skipA ? e1m : NEGV;
            const float cO5 = (skipA && skipB) ? e1m : NEGV;

            // even s0: 4-term fused LSE
            float t1 = a0 + e0p, t2 = a1m1 + cE2, t3 = a0m1 + e1m, t4 = a1m2 + cE4;
            float m0 = fmaxf(fmaxf(t1, t2), fmaxf(t3, t4));
            float na0 = m0 + lg2f(ex2f(t1 - m0) + ex2f(t2 - m0)
                                + ex2f(t3 - m0) + ex2f(t4 - m0)) + e0pp;

            // odd s1: 5-term fused LSE
            float u1 = a1 + e1p, u2 = a0 + cO2, u3 = a1m1 + cO3;
            float u4 = a0m1 + cO4, u5 = a1m2 + cO5;
            float m1 = fmaxf(fmaxf(fmaxf(u1, u2), fmaxf(u3, u4)), u5);
            float na1 = m1 + lg2f(ex2f(u1 - m1) + ex2f(u2 - m1) + ex2f(u3 - m1)
                                + ex2f(u4 - m1) + ex2f(u5 - m1)) + e1pp;

            a0 = na0; a1 = act1 ? na1 : NEGV;
        }
        s_a0[lane] = a0;
        s_a1[lane] = a1;
    } else if (wid == 1) {
        // ======== backward beta: t = T-1 .. TMID (fused) ============
        int lab  = (lane < L) ? labels[b * L + lane] : -999;
        int labn = __shfl_down_sync(0xffffffffu, lab, 1);
        const bool skipd = (lane <= 23) && (labn != lab);   // s1 -> s1+2
        unsigned skDu = __shfl_down_sync(0xffffffffu, (unsigned)skipd, 1);
        const bool skipdp1 = (lane <= 22) && skDu;
        const bool act0 = (lane <= 25);
        const bool act1 = (lane <= 24);

        const int len = lens[b];
        float b0 = (lane == len)     ? se[(T - 1) * NE]            : NEGV;
        float b1 = (lane == len - 1) ? se[(T - 1) * NE + lane + 1] : NEGV;

        {   // single step t = T-2 = 126 (verified 1-step form)
            float e0 = se[(T - 2) * NE], e1 = se[(T - 2) * NE + lane + 1];
            float q0 = __shfl_down_sync(0xffffffffu, b0, 1);
            float q1 = __shfl_down_sync(0xffffffffu, b1, 1);
            float mm0 = fmaxf(b0, b1);
            float nb0 = mm0 + lg2f(ex2f(b0 - mm0) + ex2f(b1 - mm0)) + e0;
            float c   = skipd ? q1 : NEGV;
            float mm1 = fmaxf(fmaxf(b1, q0), c);
            float nb1 = mm1
                + lg2f(ex2f(b1 - mm1) + ex2f(q0 - mm1) + ex2f(c - mm1)) + e1;
            b0 = act0 ? nb0 : NEGV;
            b1 = act1 ? nb1 : NEGV;
        }

        // 31 double steps: beta_{tt+2} -> beta_{tt}, mid emits at tt+1.
        for (int tt = T - 4; tt >= TMID; tt -= 2) {
            const float e0p = se[(tt + 1) * NE];            // E'[even]
            const float e1p = se[(tt + 1) * NE + lane + 1]; // E'[s1]
            const float e1q = se[(tt + 1) * NE + lane + 2]; // E'[s1+2] (lane+1's e1)
            const float e0t = se[tt * NE];
            const float e1t = se[tt * NE + lane + 1];

            float b0p1 = __shfl_down_sync(0xffffffffu, b0, 1);
            float b1p1 = __shfl_down_sync(0xffffffffu, b1, 1);
            float b0p2 = __shfl_down_sync(0xffffffffu, b0, 2);
            float b1p2 = __shfl_down_sync(0xffffffffu, b1, 2);
            // lanes >= 26 hold NEGV, so out-of-range shfl sources are NEGV.

            float mC = fmaxf(e0p, e1p);
            float c2 = mC + lg2f(ex2f(e0p - mC) + ex2f(e1p - mC));
            float cO3;
            if (skipd) {
                float m3 = fmaxf(fmaxf(e1p, e0p), e1q);
                cO3 = m3 + lg2f(ex2f(e1p - m3) + ex2f(e0p - m3) + ex2f(e1q - m3));
            } else cO3 = e0p;
            const float cE4 = skipd ? e1p : NEGV;
            const float cO4 = skipd ? e1q : NEGV;
            const float cO5 = (skipd && skipdp1) ? e1q : NEGV;

            // even s0: 4-term fused LSE
            float t1 = b0 + e0p, t2 = b1 + c2, t3 = b0p1 + e1p, t4 = b1p1 + cE4;
            float m0 = fmaxf(fmaxf(t1, t2), fmaxf(t3, t4));
            float nb0 = m0 + lg2f(ex2f(t1 - m0) + ex2f(t2 - m0)
                                + ex2f(t3 - m0) + ex2f(t4 - m0)) + e0t;

            // odd s1: 5-term fused LSE
            float u1 = b1 + e1p, u2 = b0p1 + c2, u3 = b1p1 + cO3;
            float u4 = b0p2 + cO4, u5 = b1p2 + cO5;
            float m1 = fmaxf(fmaxf(fmaxf(u1, u2), fmaxf(u3, u4)), u5);
            float nb1 = m1 + lg2f(ex2f(u1 - m1) + ex2f(u2 - m1) + ex2f(u3 - m1)
                                + ex2f(u4 - m1) + ex2f(u5 - m1)) + e1t;

            b0 = act0 ? nb0 : NEGV;
            b1 = act1 ? nb1 : NEGV;
        }
        s_b0[lane] = b0;
        s_b1[lane] = b1;
    }
    __syncthreads();

    if (wid == 0) {
        // combine: ll2 = LSE2_s( alpha[s] + beta[s] )
        float ta = s_a0[lane] + s_b0[lane];
        float tb = s_a1[lane] + s_b1[lane];
        float m = fmaxf(ta, tb);
#pragma unroll
        for (int o = 16; o > 0; o >>= 1)
            m = fmaxf(m, __shfl_xor_sync(0xffffffffu, m, o));
        float sum = ex2f(ta - m) + ex2f(tb - m);
#pragma unroll
        for (int o = 16; o > 0; o >>= 1)
            sum += __shfl_xor_sync(0xffffffffu, sum, o);
        if (lane == 0) {
            int len = lens[b];
            float ll = (m + lg2f(sum)) * LN2;
            float loss = -ll;
            if (!(loss <= 1e29f)) loss = 0.f;       // zero_infinity (inf/nan)
            g_partial[b] = loss / (float)len;
        }
    }

    // ----- last-arriving block (of 128) does the final reduce -----
    __syncthreads();
    if (tid == 0) {
        __threadfence();
        int old = atomicAdd(&g_dpcnt, 1);
        s_flag = ((old % B) == B - 1);
    }
    __syncthreads();
    if (!s_flag) return;
    __threadfence();                                // acquire peer partials

    float pv = g_partial[tid];
#pragma unroll
    for (int o = 16; o > 0; o >>= 1)
        pv += __shfl_xor_sync(0xffffffffu, pv, o);
    if (lane == 0) s_fin[wid] = pv;
    __syncthreads();
    if (tid == 0)
        out[0] = (s_fin[0] + s_fin[1] + s_fin[2] + s_fin[3])
                 / ((float)B * (float)B);
}

// ---------------------------------------------------------------------------
extern "C" void kernel_launch(void* const* d_in, const int* in_sizes, int n_in,
                              void* d_out, int out_size)
{
    const float* pred   = (const float*)d_in[0];
    const int*   labels = (const int*)d_in[1];
    const int*   lens   = (const int*)d_in[2];
    float*       out    = (float*)d_out;

    k_lse_gather<<<GRID1, 256>>>(pred, labels);
    k_ctc_dp<<<B, 128>>>(labels, lens, out);
}